// round 16
// baseline (speedup 1.0000x reference)
#include <cuda_runtime.h>
#include <cuda_fp16.h>
#include <math.h>
#include <stdint.h>

// ---------------- problem constants ----------------
namespace {
constexpr int kB  = 4;
constexpr int kN  = 1024;
constexpr int kD  = 768;
constexpr int kH  = 12;
constexpr int kHD = 64;
constexpr int kGP = 49;
constexpr int kMLP = 3072;
constexpr int kT  = kB * kN;     // 4096 tokens
constexpr int kBH = kB * kH;     // 48 batched heads
constexpr int kQD = 3 * kD;      // 2304
constexpr int kGemmSmemH = 3 * (128 * 40 + 128 * 40) * 2;
}

// ---------------- scratch (device globals: no allocation allowed) ----------------
__device__ __half g_xn  [kT * kD];
__device__ __half g_qkvh[kT * kQD];
__device__ __half g_S   [(size_t)kBH * kN * kN];
__device__ __half g_G   [(size_t)kBH * kN * kN];
__device__ __half g_gw  [kBH * kN * 64];
__device__ float  g_inv [kBH * kN];
__device__ __half g_vs  [(size_t)kBH * kHD * kN];
__device__ __half g_ctx [kT * kD];
__device__ float  g_y   [kT * kD];
__device__ __half g_yn  [kT * kD];
__device__ __half g_hdn [kT * kMLP];
__device__ __half g_qkvwt[kQD * kD];
__device__ __half g_projwt[kD * kD];
__device__ __half g_ff1wt [kMLP * kD];
__device__ __half g_ff2wt [kD * kMLP];

__device__ __forceinline__ float gelu_exact(float x) {
    return 0.5f * x * (1.0f + erff(x * 0.70710678118654752440f));
}

__device__ __forceinline__ void cp16(void* dst_smem, const void* src_gmem) {
    uint32_t d = (uint32_t)__cvta_generic_to_shared(dst_smem);
    asm volatile("cp.async.cg.shared.global [%0], [%1], 16;" :: "r"(d), "l"(src_gmem));
}
__device__ __forceinline__ void cp_commit() {
    asm volatile("cp.async.commit_group;");
}
__device__ __forceinline__ void cp_wait0() {
    asm volatile("cp.async.wait_group 0;");
}
__device__ __forceinline__ void cp_wait1() {
    asm volatile("cp.async.wait_group 1;");
}

// ldmatrix x4 (non-trans)
__device__ __forceinline__ void ldsm_x4(uint32_t* r, uint32_t smem_addr) {
    asm volatile("ldmatrix.sync.aligned.m8n8.x4.shared.b16 {%0,%1,%2,%3}, [%4];"
                 : "=r"(r[0]), "=r"(r[1]), "=r"(r[2]), "=r"(r[3])
                 : "r"(smem_addr));
}

// D += A(m16k16,row,f16) * B(k16n8,col,f16), fp32 accum
__device__ __forceinline__ void mma16h(float* c, const uint32_t* a, const uint32_t* b) {
    asm volatile("mma.sync.aligned.m16n8k16.row.col.f32.f16.f16.f32 "
                 "{%0,%1,%2,%3}, {%4,%5,%6,%7}, {%8,%9}, {%0,%1,%2,%3};"
                 : "+f"(c[0]), "+f"(c[1]), "+f"(c[2]), "+f"(c[3])
                 : "r"(a[0]), "r"(a[1]), "r"(a[2]), "r"(a[3]),
                   "r"(b[0]), "r"(b[1]));
}

// ------- weight transpose+convert: Wt[n][k] = (half)W[k][n] ------------------
__global__ __launch_bounds__(256) void wt_kernel(const float* __restrict__ W,
                                                 __half* __restrict__ Wt,
                                                 int K, int N) {
    __shared__ float tile[32][33];
    int k0 = blockIdx.x * 32, n0 = blockIdx.y * 32;
    int t = threadIdx.x;
    int i = t & 31, j0 = t >> 5;
#pragma unroll
    for (int jj = 0; jj < 32; jj += 8)
        tile[j0 + jj][i] = W[(size_t)(k0 + j0 + jj) * N + n0 + i];
    __syncthreads();
#pragma unroll
    for (int jj = 0; jj < 32; jj += 8)
        Wt[(size_t)(n0 + j0 + jj) * K + k0 + i] = __float2half_rn(tile[i][j0 + jj]);
}

// ---------------- LayerNorm: fp32 in, fp16 out; one block per row -------------
__global__ __launch_bounds__(256) void ln_kernel(const float* __restrict__ x,
                                                 const float* __restrict__ w,
                                                 const float* __restrict__ b,
                                                 __half* __restrict__ out) {
    __shared__ float sh1[8], sh2[8];
    int row = blockIdx.x;
    int t = threadIdx.x;
    const float* xr = x + (size_t)row * kD;
    float v[3];
    float s = 0.f, s2 = 0.f;
#pragma unroll
    for (int i = 0; i < 3; i++) {
        v[i] = xr[t + i * 256];
        s  += v[i];
        s2 += v[i] * v[i];
    }
#pragma unroll
    for (int o = 16; o; o >>= 1) {
        s  += __shfl_xor_sync(0xffffffffu, s, o);
        s2 += __shfl_xor_sync(0xffffffffu, s2, o);
    }
    if ((t & 31) == 0) { sh1[t >> 5] = s; sh2[t >> 5] = s2; }
    __syncthreads();
    s = sh1[t & 7]; s2 = sh2[t & 7];
#pragma unroll
    for (int o = 4; o; o >>= 1) {
        s  += __shfl_xor_sync(0xffffffffu, s, o);
        s2 += __shfl_xor_sync(0xffffffffu, s2, o);
    }
    float mu   = s * (1.0f / kD);
    float var  = fmaxf(s2 * (1.0f / kD) - mu * mu, 0.f);
    float rstd = rsqrtf(var + 1e-5f);
    __half* orow = out + (size_t)row * kD;
#pragma unroll
    for (int i = 0; i < 3; i++) {
        int c = t + i * 256;
        orow[c] = __float2half_rn((v[i] - mu) * rstd * w[c] + b[c]);
    }
}

// ------- FP16 GEMM (NT): C[M,N] = A[M,K] @ Bt[N,K]^T + bias (+gelu)(+res) ----
// 128x128 block, 8 warps, K-step 32, 3-stage cp.async, ldmatrix; 2 blocks/SM.
__global__ __launch_bounds__(256, 2) void gemm_f16_nt(
        const __half* __restrict__ A, const __half* __restrict__ Bt,
        const float* __restrict__ bias, const float* __restrict__ res,
        void* __restrict__ Cout, int M, int N, int K, int act, int outHalf) {
    extern __shared__ __half hsm[];
    __half* AsBuf = hsm;
    __half* BsBuf = hsm + 3 * 128 * 40;
    uint32_t asBase = (uint32_t)__cvta_generic_to_shared(AsBuf);
    uint32_t bsBase = (uint32_t)__cvta_generic_to_shared(BsBuf);
#define HAS(s, r, c) AsBuf[(s) * 5120 + (r) * 40 + (c)]
#define HBS(s, r, c) BsBuf[(s) * 5120 + (r) * 40 + (c)]
    int tid = threadIdx.x, lane = tid & 31, warp = tid >> 5;
    int g = lane >> 2, tg = lane & 3;
    int lr = lane & 7, sel = lane >> 3;
    int wm = (warp >> 1) * 32, wn = (warp & 1) * 64;
    int row0 = blockIdx.y * 128, col0 = blockIdx.x * 128;
    int ra = tid >> 1, cha = (tid & 1) * 16;
    const __half* Ap = A  + (size_t)(row0 + ra) * K + cha;
    const __half* Bp = Bt + (size_t)(col0 + ra) * K + cha;
    float acc[2][8][4] = {};

    auto issue = [&](int k0, int s) {
        if (k0 < K) {
            cp16(&HAS(s, ra, cha),     Ap + k0);
            cp16(&HAS(s, ra, cha + 8), Ap + k0 + 8);
            cp16(&HBS(s, ra, cha),     Bp + k0);
            cp16(&HBS(s, ra, cha + 8), Bp + k0 + 8);
        }
        cp_commit();
    };
    issue(0, 0);
    issue(32, 1);
    int s = 0;
    for (int k0 = 0; k0 < K; k0 += 32) {
        cp_wait1();
        __syncthreads();
        int s2n = s + 2 >= 3 ? s - 1 : s + 2;
        issue(k0 + 64, s2n);
#pragma unroll
        for (int k16 = 0; k16 < 32; k16 += 16) {
            uint32_t af[2][4], bf[8][2];
#pragma unroll
            for (int mi = 0; mi < 2; mi++) {
                int r = wm + mi * 16 + lr + (sel & 1) * 8;
                int c = k16 + (sel >> 1) * 8;
                ldsm_x4(af[mi], asBase + (s * 5120 + r * 40 + c) * 2);
            }
#pragma unroll
            for (int njp = 0; njp < 4; njp++) {
                int n = wn + njp * 16 + lr + (sel >> 1) * 8;
                int c = k16 + (sel & 1) * 8;
                uint32_t tmp[4];
                ldsm_x4(tmp, bsBase + (s * 5120 + n * 40 + c) * 2);
                bf[njp * 2][0] = tmp[0];     bf[njp * 2][1] = tmp[1];
                bf[njp * 2 + 1][0] = tmp[2]; bf[njp * 2 + 1][1] = tmp[3];
            }
#pragma unroll
            for (int mi = 0; mi < 2; mi++)
#pragma unroll
                for (int nj = 0; nj < 8; nj++)
                    mma16h(acc[mi][nj], af[mi], bf[nj]);
        }
        s = s + 1 >= 3 ? 0 : s + 1;
    }
#undef HAS
#undef HBS
#pragma unroll
    for (int mi = 0; mi < 2; mi++) {
#pragma unroll
        for (int nj = 0; nj < 8; nj++) {
            int r0 = row0 + wm + mi * 16 + g;
            int c = col0 + wn + nj * 8 + tg * 2;
            float b0 = bias[c], b1 = bias[c + 1];
            float o00 = acc[mi][nj][0] + b0, o01 = acc[mi][nj][1] + b1;
            float o10 = acc[mi][nj][2] + b0, o11 = acc[mi][nj][3] + b1;
            if (act) {
                o00 = gelu_exact(o00); o01 = gelu_exact(o01);
                o10 = gelu_exact(o10); o11 = gelu_exact(o11);
            }
            if (res) {
                o00 += res[(size_t)r0 * N + c];       o01 += res[(size_t)r0 * N + c + 1];
                o10 += res[(size_t)(r0 + 8) * N + c]; o11 += res[(size_t)(r0 + 8) * N + c + 1];
            }
            if (outHalf) {
                __half* C = (__half*)Cout;
                *(__half2*)&C[(size_t)r0 * N + c]       = __floats2half2_rn(o00, o01);
                *(__half2*)&C[(size_t)(r0 + 8) * N + c] = __floats2half2_rn(o10, o11);
            } else {
                float* C = (float*)Cout;
                *(float2*)&C[(size_t)r0 * N + c]       = make_float2(o00, o01);
                *(float2*)&C[(size_t)(r0 + 8) * N + c] = make_float2(o10, o11);
            }
        }
    }
}

// ---- batched NT fp16 GEMM, K=64 fixed: C[bh] = scale * A[bh] @ B[bh]^T ------
__global__ __launch_bounds__(256, 2) void nt64_f16(
        const __half* __restrict__ Abase, const __half* __restrict__ Bbase,
        size_t batchStr, size_t headStr, int rowStr, float scale,
        __half* __restrict__ C) {
    __shared__ __align__(16) __half As[128][72];
    __shared__ __align__(16) __half Bs[128][72];
    uint32_t asBase = (uint32_t)__cvta_generic_to_shared(&As[0][0]);
    uint32_t bsBase = (uint32_t)__cvta_generic_to_shared(&Bs[0][0]);
    int bh = blockIdx.z, b = bh / kH, h = bh % kH;
    const __half* Ab = Abase + (size_t)b * batchStr + (size_t)h * headStr;
    const __half* Bb = Bbase + (size_t)b * batchStr + (size_t)h * headStr;
    int tid = threadIdx.x, lane = tid & 31, warp = tid >> 5;
    int g = lane >> 2, tg = lane & 3;
    int lr = lane & 7, sel = lane >> 3;
    int wm = (warp >> 1) * 32, wn = (warp & 1) * 64;
    int n0 = blockIdx.y * 128, m0 = blockIdx.x * 128;
    for (int i = tid; i < 1024; i += 256) {
        int r = i >> 3, ch = (i & 7) * 8;
        cp16(&As[r][ch], Ab + (size_t)(n0 + r) * rowStr + ch);
        cp16(&Bs[r][ch], Bb + (size_t)(m0 + r) * rowStr + ch);
    }
    cp_commit();
    cp_wait0();
    __syncthreads();
    float acc[2][8][4] = {};
#pragma unroll
    for (int k16 = 0; k16 < 64; k16 += 16) {
        uint32_t af[2][4], bf[8][2];
#pragma unroll
        for (int mi = 0; mi < 2; mi++) {
            int r = wm + mi * 16 + lr + (sel & 1) * 8;
            int c = k16 + (sel >> 1) * 8;
            ldsm_x4(af[mi], asBase + (r * 72 + c) * 2);
        }
#pragma unroll
        for (int njp = 0; njp < 4; njp++) {
            int n = wn + njp * 16 + lr + (sel >> 1) * 8;
            int c = k16 + (sel & 1) * 8;
            uint32_t tmp[4];
            ldsm_x4(tmp, bsBase + (n * 72 + c) * 2);
            bf[njp * 2][0] = tmp[0];     bf[njp * 2][1] = tmp[1];
            bf[njp * 2 + 1][0] = tmp[2]; bf[njp * 2 + 1][1] = tmp[3];
        }
#pragma unroll
        for (int mi = 0; mi < 2; mi++)
#pragma unroll
            for (int nj = 0; nj < 8; nj++)
                mma16h(acc[mi][nj], af[mi], bf[nj]);
    }
    __half* Cb = C + (size_t)bh * kN * kN;
#pragma unroll
    for (int mi = 0; mi < 2; mi++) {
#pragma unroll
        for (int nj = 0; nj < 8; nj++) {
            int r0 = n0 + wm + mi * 16 + g;
            int c = m0 + wn + nj * 8 + tg * 2;
            *(__half2*)&Cb[(size_t)r0 * kN + c] =
                __floats2half2_rn(acc[mi][nj][0] * scale, acc[mi][nj][1] * scale);
            *(__half2*)&Cb[(size_t)(r0 + 8) * kN + c] =
                __floats2half2_rn(acc[mi][nj][2] * scale, acc[mi][nj][3] * scale);
        }
    }
}

// ------- per-row: P = softmax(S*G); A = (1-a)P + a*G  (all fp16 storage) -----
__global__ __launch_bounds__(256) void rowmix_kernel(const float* __restrict__ alpha,
                                                     __half* __restrict__ S,
                                                     const __half* __restrict__ G) {
    __shared__ float sh1[8];
    int gr = blockIdx.x;                 // bh*N + n
    int h = (gr >> 10) % kH;
    size_t off = (size_t)gr * kN;
    int t = threadIdx.x;
    float a = 1.f / (1.f + __expf(-alpha[h]));
    __half2* Sh = (__half2*)(S + off);
    const __half2* Gh = (const __half2*)(G + off);
    __half2 p0 = Sh[t * 2], p1 = Sh[t * 2 + 1];
    __half2 q0 = Gh[t * 2], q1 = Gh[t * 2 + 1];
    float2 f0 = __half22float2(p0), f1 = __half22float2(p1);
    float2 g0 = __half22float2(q0), g1 = __half22float2(q1);
    float gv[4] = { g0.x, g0.y, g1.x, g1.y };
    float tv[4] = { f0.x * gv[0], f0.y * gv[1], f1.x * gv[2], f1.y * gv[3] };
    float mx = fmaxf(fmaxf(tv[0], tv[1]), fmaxf(tv[2], tv[3]));
    for (int o = 16; o; o >>= 1) mx = fmaxf(mx, __shfl_xor_sync(0xffffffffu, mx, o));
    if ((t & 31) == 0) sh1[t >> 5] = mx;
    __syncthreads();
    mx = sh1[t & 7];
    for (int o = 4; o; o >>= 1) mx = fmaxf(mx, __shfl_xor_sync(0xffffffffu, mx, o));
    __syncthreads();
    float e[4], sum = 0.f;
#pragma unroll
    for (int i = 0; i < 4; i++) { e[i] = __expf(tv[i] - mx); sum += e[i]; }
    for (int o = 16; o; o >>= 1) sum += __shfl_xor_sync(0xffffffffu, sum, o);
    if ((t & 31) == 0) sh1[t >> 5] = sum;
    __syncthreads();
    sum = sh1[t & 7];
    for (int o = 4; o; o >>= 1) sum += __shfl_xor_sync(0xffffffffu, sum, o);
    float isum = (1.f - a) / sum;
    Sh[t * 2]     = __floats2half2_rn(e[0] * isum + a * gv[0], e[1] * isum + a * gv[1]);
    Sh[t * 2 + 1] = __floats2half2_rn(e[2] * isum + a * gv[2], e[3] * isum + a * gv[3]);
}

// ------- column sums over n (axis=2), fp16 A, stores 1/(sum+1e-8) -------
__global__ __launch_bounds__(256) void colsum_kernel(const __half* __restrict__ Sa,
                                                     float* __restrict__ inv) {
    int idx = blockIdx.x * 256 + threadIdx.x;   // bh*N + m
    int bh = idx >> 10, m = idx & 1023;
    const __half* p = Sa + (size_t)bh * kN * kN + m;
    float s0 = 0.f, s1 = 0.f, s2 = 0.f, s3 = 0.f;
    float s4 = 0.f, s5 = 0.f, s6 = 0.f, s7 = 0.f;
    float s8 = 0.f, s9 = 0.f, sa = 0.f, sb = 0.f;
    float sc = 0.f, sd = 0.f, se = 0.f, sf = 0.f;
#pragma unroll 2
    for (int n = 0; n < kN; n += 16) {
        s0 += __half2float(p[(size_t)(n + 0) * kN]);
        s1 += __half2float(p[(size_t)(n + 1) * kN]);
        s2 += __half2float(p[(size_t)(n + 2) * kN]);
        s3 += __half2float(p[(size_t)(n + 3) * kN]);
        s4 += __half2float(p[(size_t)(n + 4) * kN]);
        s5 += __half2float(p[(size_t)(n + 5) * kN]);
        s6 += __half2float(p[(size_t)(n + 6) * kN]);
        s7 += __half2float(p[(size_t)(n + 7) * kN]);
        s8 += __half2float(p[(size_t)(n + 8) * kN]);
        s9 += __half2float(p[(size_t)(n + 9) * kN]);
        sa += __half2float(p[(size_t)(n + 10) * kN]);
        sb += __half2float(p[(size_t)(n + 11) * kN]);
        sc += __half2float(p[(size_t)(n + 12) * kN]);
        sd += __half2float(p[(size_t)(n + 13) * kN]);
        se += __half2float(p[(size_t)(n + 14) * kN]);
        sf += __half2float(p[(size_t)(n + 15) * kN]);
    }
    float s = (((s0 + s1) + (s2 + s3)) + ((s4 + s5) + (s6 + s7)))
            + (((s8 + s9) + (sa + sb)) + ((sc + sd) + (se + sf)));
    inv[idx] = 1.f / (s + 1e-8f);
}

// ------- vs[bh][d][k] = V[b,k,h,d] * inv[bh,k]   (fp16 in, transposed fp16) --
__global__ __launch_bounds__(256) void vscale_t_kernel(const __half* __restrict__ qkvh,
                                                       const float* __restrict__ inv,
                                                       __half* __restrict__ vs) {
    __shared__ __half tile[64][72];
    int bh = blockIdx.y, k0 = blockIdx.x * 64;
    int b = bh / kH, h = bh % kH;
    int t = threadIdx.x;
    for (int i = t; i < 64 * 16; i += 256) {
        int kk = i >> 4, d4 = (i & 15) * 4;
        float iv = inv[bh * kN + k0 + kk];
        const __half* src = qkvh + (size_t)(b * kN + k0 + kk) * kQD + 2 * kD + h * kHD + d4;
        __half2 h01 = *(const __half2*)(src);
        __half2 h23 = *(const __half2*)(src + 2);
        float2 f01 = __half22float2(h01), f23 = __half22float2(h23);
        tile[d4 + 0][kk] = __float2half_rn(f01.x * iv);
        tile[d4 + 1][kk] = __float2half_rn(f01.y * iv);
        tile[d4 + 2][kk] = __float2half_rn(f23.x * iv);
        tile[d4 + 3][kk] = __float2half_rn(f23.y * iv);
    }
    __syncthreads();
    for (int i = t; i < 64 * 8; i += 256) {
        int d = i >> 3, ch = (i & 7) * 8;
        *(uint4*)(vs + ((size_t)bh * kHD + d) * kN + k0 + ch) = *(uint4*)&tile[d][ch];
    }
}

// ------- out = A @ Vs (fp16 m16n8k16, fp32 accum), ldmatrix, ctx fp16 --------
__global__ __launch_bounds__(256, 2) void av_f16(const __half* __restrict__ Sa,
                                                 const __half* __restrict__ vs,
                                                 __half* __restrict__ ctx) {
    __shared__ __align__(16) __half As[3][128][24];
    __shared__ __align__(16) __half Bs[3][64][24];
    uint32_t asBase = (uint32_t)__cvta_generic_to_shared(&As[0][0][0]);
    uint32_t bsBase = (uint32_t)__cvta_generic_to_shared(&Bs[0][0][0]);
    int bh = blockIdx.z, b = bh / kH, h = bh % kH;
    const __half* Ab = Sa + (size_t)bh * kN * kN;
    const __half* vb = vs + (size_t)bh * kHD * kN;
    int tid = threadIdx.x, lane = tid & 31, warp = tid >> 5;
    int g = lane >> 2, tg = lane & 3;
    int lr = lane & 7, sel = lane >> 3;
    int wm = (warp >> 1) * 32, wn = (warp & 1) * 32;
    int row0 = blockIdx.y * 128;
    int ra = tid >> 1, cha = (tid & 1) * 8;
    int db = (tid & 127) >> 1, chb = (tid & 1) * 8;
    const __half* Ap = Ab + (size_t)(row0 + ra) * kN + cha;
    const __half* Vp = vb + (size_t)db * kN + chb;
    float acc[2][4][4] = {};
    auto issue = [&](int k0, int s) {
        if (k0 < kN) {
            cp16(&As[s][ra][cha], Ap + k0);
            if (tid < 128) cp16(&Bs[s][db][chb], Vp + k0);
        }
        cp_commit();
    };
    issue(0, 0);
    issue(16, 1);
    int s = 0;
    for (int k0 = 0; k0 < kN; k0 += 16) {
        cp_wait1();
        __syncthreads();
        int s2n = s + 2 >= 3 ? s - 1 : s + 2;
        issue(k0 + 32, s2n);
        uint32_t af[2][4], bf[4][2];
#pragma unroll
        for (int mi = 0; mi < 2; mi++) {
            int r = wm + mi * 16 + lr + (sel & 1) * 8;
            int c = (sel >> 1) * 8;
            ldsm_x4(af[mi], asBase + (s * 128 * 24 + r * 24 + c) * 2);
        }
#pragma unroll
        for (int njp = 0; njp < 2; njp++) {
            int n = wn + njp * 16 + lr + (sel >> 1) * 8;
            int c = (sel & 1) * 8;
            uint32_t tmp[4];
            ldsm_x4(tmp, bsBase + (s * 64 * 24 + n * 24 + c) * 2);
            bf[njp * 2][0] = tmp[0];     bf[njp * 2][1] = tmp[1];
            bf[njp * 2 + 1][0] = tmp[2]; bf[njp * 2 + 1][1] = tmp[3];
        }
#pragma unroll
        for (int mi = 0; mi < 2; mi++)
#pragma unroll
            for (int nj = 0; nj < 4; nj++)
                mma16h(acc[mi][nj], af[mi], bf[nj]);
        s = s + 1 >= 3 ? 0 : s + 1;
    }
#pragma unroll
    for (int mi = 0; mi < 2; mi++) {
#pragma unroll
        for (int nj = 0; nj < 4; nj++) {
            int tok0 = b * kN + row0 + wm + mi * 16 + g;
            int c = h * kHD + wn + nj * 8 + tg * 2;
            *(__half2*)&ctx[(size_t)tok0 * kD + c] =
                __floats2half2_rn(acc[mi][nj][0], acc[mi][nj][1]);
            *(__half2*)&ctx[(size_t)(tok0 + 8) * kD + c] =
                __floats2half2_rn(acc[mi][nj][2], acc[mi][nj][3]);
        }
    }
}

// ---- group weights: gw = softmax(gelu(V @ gp^T)), fp16 in/out, pad to 64 ----
__global__ __launch_bounds__(256) void gw_kernel(const __half* __restrict__ qkvh,
                                                 const float* __restrict__ gp_w,
                                                 __half* __restrict__ gw) {
    __shared__ __align__(16) float gps[kGP][68];
    __shared__ __align__(16) float Vs[64][68];
    int bh = blockIdx.y;
    int b = bh / kH, h = bh % kH;
    int n0 = blockIdx.x * 64;
    int tid = threadIdx.x;
    const float* gph = gp_w + (size_t)h * kGP * kHD;
    for (int i = tid; i < kGP * 16; i += 256) {
        int r = i >> 4, c4 = (i & 15) * 4;
        *(float4*)&gps[r][c4] = *(const float4*)(gph + r * kHD + c4);
    }
    const __half* vb = qkvh + (size_t)(b * kN + n0) * kQD + 2 * kD + h * kHD;
    for (int i = tid; i < 64 * 16; i += 256) {
        int r = i >> 4, c4 = (i & 15) * 4;
        __half2 h01 = *(const __half2*)(vb + (size_t)r * kQD + c4);
        __half2 h23 = *(const __half2*)(vb + (size_t)r * kQD + c4 + 2);
        float2 f01 = __half22float2(h01), f23 = __half22float2(h23);
        Vs[r][c4 + 0] = f01.x; Vs[r][c4 + 1] = f01.y;
        Vs[r][c4 + 2] = f23.x; Vs[r][c4 + 3] = f23.y;
    }
    __syncthreads();
    int r = tid >> 2;
    int c0 = tid & 3;
    float val[13];
    float mx = -1e30f;
#pragma unroll
    for (int j = 0; j < 13; j++) {
        int c = c0 + 4 * j;
        float acc = 0.f;
        if (c < kGP) {
#pragma unroll
            for (int d = 0; d < kHD; d += 4) {
                float4 vv = *(const float4*)&Vs[r][d];
                float4 gg = *(const float4*)&gps[c][d];
                acc += vv.x * gg.x + vv.y * gg.y + vv.z * gg.z + vv.w * gg.w;
            }
            acc = gelu_exact(acc);
            mx = fmaxf(mx, acc);
        }
        val[j] = acc;
    }
    mx = fmaxf(mx, __shfl_xor_sync(0xffffffffu, mx, 1));
    mx = fmaxf(mx, __shfl_xor_sync(0xffffffffu, mx, 2));
    float sum = 0.f;
#pragma unroll
    for (int j = 0; j < 13; j++) {
        int c = c0 + 4 * j;
        val[j] = (c < kGP) ? __expf(val[j] - mx) : 0.f;
        sum += val[j];
    }
    sum += __shfl_xor_sync(0xffffffffu, sum, 1);
    sum += __shfl_xor_sync(0xffffffffu, sum, 2);
    float is = 1.f / sum;
    __half* grow = gw + (size_t)(bh * kN + n0 + r) * 64;
#pragma unroll
    for (int j = 0; j < 16; j++) {
        int c = c0 + 4 * j;
        if (c < 64)
            grow[c] = __float2half_rn((j < 13 && c < kGP) ? val[j] * is : 0.f);
    }
}

// ---------------- launch ----------------
extern "C" void kernel_launch(void* const* d_in, const int* in_sizes, int n_in,
                              void* d_out, int out_size) {
    const float* x      = (const float*)d_in[0];
    const float* ln1_w  = (const float*)d_in[1];
    const float* ln1_b  = (const float*)d_in[2];
    const float* qkv_w  = (const float*)d_in[3];
    const float* qkv_b  = (const float*)d_in[4];
    const float* proj_w = (const float*)d_in[5];
    const float* proj_b = (const float*)d_in[6];
    const float* gp_w   = (const float*)d_in[7];
    const float* alpha  = (const float*)d_in[8];
    const float* ln2_w  = (const float*)d_in[9];
    const float* ln2_b  = (const float*)d_in[10];
    const float* ff1_w  = (const float*)d_in[11];
    const float* ff1_b  = (const float*)d_in[12];
    const float* ff2_w  = (const float*)d_in[13];
    const float* ff2_b  = (const float*)d_in[14];
    float* out = (float*)d_out;

    float *inv, *y;
    __half *xn, *qkvh, *S, *G, *gw, *vs, *ctx, *yn, *hdn;
    __half *qkvwt, *projwt, *ff1wt, *ff2wt;
    cudaGetSymbolAddress((void**)&xn,   g_xn);
    cudaGetSymbolAddress((void**)&qkvh, g_qkvh);
    cudaGetSymbolAddress((void**)&S,    g_S);
    cudaGetSymbolAddress((void**)&G,    g_G);
    cudaGetSymbolAddress((void**)&gw,   g_gw);
    cudaGetSymbolAddress((void**)&inv,  g_inv);
    cudaGetSymbolAddress((void**)&vs,   g_vs);
    cudaGetSymbolAddress((void**)&ctx,  g_ctx);
    cudaGetSymbolAddress((void**)&y,    g_y);
    cudaGetSymbolAddress((void**)&yn,   g_yn);
    cudaGetSymbolAddress((void**)&hdn,  g_hdn);
    cudaGetSymbolAddress((void**)&qkvwt,  g_qkvwt);
    cudaGetSymbolAddress((void**)&projwt, g_projwt);
    cudaGetSymbolAddress((void**)&ff1wt,  g_ff1wt);
    cudaGetSymbolAddress((void**)&ff2wt,  g_ff2wt);

    cudaFuncSetAttribute(gemm_f16_nt,
                         cudaFuncAttributeMaxDynamicSharedMemorySize, kGemmSmemH);

    // weight transposes (fp32 -> fp16, [K][N] -> [N][K])
    wt_kernel<<<dim3(kD / 32, kQD / 32), 256>>>(qkv_w, qkvwt, kD, kQD);
    wt_kernel<<<dim3(kD / 32, kD / 32), 256>>>(proj_w, projwt, kD, kD);
    wt_kernel<<<dim3(kD / 32, kMLP / 32), 256>>>(ff1_w, ff1wt, kD, kMLP);
    wt_kernel<<<dim3(kMLP / 32, kD / 32), 256>>>(ff2_w, ff2wt, kMLP, kD);

    // attention branch
    ln_kernel<<<kT, 256>>>(x, ln1_w, ln1_b, xn);
    gemm_f16_nt<<<dim3(kQD / 128, kT / 128), 256, kGemmSmemH>>>(
        xn, qkvwt, qkv_b, nullptr, qkvh, kT, kQD, kD, 0, 1);
    nt64_f16<<<dim3(8, 8, kBH), 256>>>(qkvh, qkvh + kD,
                                       (size_t)kN * kQD, (size_t)kHD, kQD, 0.125f, S);
    gw_kernel<<<dim3(kN / 64, kBH), 256>>>(qkvh, gp_w, gw);
    nt64_f16<<<dim3(8, 8, kBH), 256>>>(gw, gw,
                                       (size_t)kH * kN * 64, (size_t)kN * 64, 64, 1.0f, G);
    rowmix_kernel<<<kBH * kN, 256>>>(alpha, S, G);
    colsum_kernel<<<kBH * kN / 256, 256>>>(S, inv);
    vscale_t_kernel<<<dim3(kN / 64, kBH), 256>>>(qkvh, inv, vs);
    av_f16<<<dim3(1, 8, kBH), 256>>>(S, vs, ctx);
    gemm_f16_nt<<<dim3(kD / 128, kT / 128), 256, kGemmSmemH>>>(
        ctx, projwt, proj_b, x, y, kT, kD, kD, 0, 0);
    // FFN branch
    ln_kernel<<<kT, 256>>>(y, ln2_w, ln2_b, yn);
    gemm_f16_nt<<<dim3(kMLP / 128, kT / 128), 256, kGemmSmemH>>>(
        yn, ff1wt, ff1_b, nullptr, hdn, kT, kMLP, kD, 1, 1);
    gemm_f16_nt<<<dim3(kD / 128, kT / 128), 256, kGemmSmemH>>>(
        hdn, ff2wt, ff2_b, y, out, kT, kD, kMLP, 0, 0);
}